// round 8
// baseline (speedup 1.0000x reference)
#include <cuda_runtime.h>
#include <cuda_bf16.h>
#include <math.h>
#include <stdint.h>

// Problem constants
#define Bn 8
#define Nn 1025
#define Cc 512
#define Hh 8
#define HD 64
#define Mrows (Bn*Nn)   // 8200

// Scratch: device globals (no cudaMalloc allowed)
__device__ __nv_bfloat16 g_qh[(size_t)Bn*Hh*Nn*HD];
__device__ __nv_bfloat16 g_ql[(size_t)Bn*Hh*Nn*HD];
__device__ __nv_bfloat16 g_kh[(size_t)Bn*Hh*Nn*HD];
__device__ __nv_bfloat16 g_kl[(size_t)Bn*Hh*Nn*HD];
__device__ __nv_bfloat16 g_vh[(size_t)Bn*Hh*Nn*HD];
__device__ __nv_bfloat16 g_vl[(size_t)Bn*Hh*Nn*HD];
__device__ float g_att[(size_t)Bn*Nn*Cc];      // (b,n,c) pre-projection
__device__ float g_tab[Hh*32*32];              // bias table, pre-scaled by log2(e)

// ==========================================================================
// Helpers (base-target PTX only: mma.sync / ldmatrix / cp.async)
// ==========================================================================
__device__ __forceinline__ uint32_t smem_u32(const void* p) {
    uint32_t a;
    asm("{ .reg .u64 t; cvta.to.shared.u64 t, %1; cvt.u32.u64 %0, t; }" : "=r"(a) : "l"(p));
    return a;
}
__device__ __forceinline__ void ldsm4(uint32_t* r, uint32_t a) {
    asm volatile("ldmatrix.sync.aligned.m8n8.x4.shared.b16 {%0,%1,%2,%3}, [%4];"
        : "=r"(r[0]), "=r"(r[1]), "=r"(r[2]), "=r"(r[3]) : "r"(a));
}
__device__ __forceinline__ void ldsm4t(uint32_t* r, uint32_t a) {
    asm volatile("ldmatrix.sync.aligned.m8n8.x4.trans.shared.b16 {%0,%1,%2,%3}, [%4];"
        : "=r"(r[0]), "=r"(r[1]), "=r"(r[2]), "=r"(r[3]) : "r"(a));
}
__device__ __forceinline__ void mma_bf16(float* c, const uint32_t* a, const uint32_t* b) {
    asm volatile("mma.sync.aligned.m16n8k16.row.col.f32.bf16.bf16.f32 "
        "{%0,%1,%2,%3}, {%4,%5,%6,%7}, {%8,%9}, {%0,%1,%2,%3};"
        : "+f"(c[0]), "+f"(c[1]), "+f"(c[2]), "+f"(c[3])
        : "r"(a[0]), "r"(a[1]), "r"(a[2]), "r"(a[3]), "r"(b[0]), "r"(b[1]));
}
__device__ __forceinline__ float ex2f(float x) {
    float y; asm("ex2.approx.f32 %0, %1;" : "=f"(y) : "f"(x)); return y;
}
__device__ __forceinline__ uint32_t pack_hi2(float a, float b, float& ra, float& rb) {
    __nv_bfloat16 ha = __float2bfloat16_rn(a);
    __nv_bfloat16 hb = __float2bfloat16_rn(b);
    ra = a - __bfloat162float(ha);
    rb = b - __bfloat162float(hb);
    __nv_bfloat162 p(ha, hb);
    return *reinterpret_cast<uint32_t*>(&p);
}
__device__ __forceinline__ uint32_t pack2(float a, float b) {
    __nv_bfloat162 p(__float2bfloat16_rn(a), __float2bfloat16_rn(b));
    return *reinterpret_cast<uint32_t*>(&p);
}
__device__ __forceinline__ void cp16(uint32_t dst, const void* src, bool valid) {
    int sz = valid ? 16 : 0;
    asm volatile("cp.async.cg.shared.global [%0], [%1], 16, %2;"
        :: "r"(dst), "l"(src), "r"(sz) : "memory");
}
#define CP_COMMIT() asm volatile("cp.async.commit_group;" ::: "memory")
#define CP_WAIT(N)  asm volatile("cp.async.wait_group %0;" :: "n"(N) : "memory")

// ==========================================================================
// Bias table (collapsed geometry): stored pre-multiplied by log2(e)
// ==========================================================================
__global__ void tab_kernel(const float* __restrict__ wg_w,
                           const float* __restrict__ wg_b) {
    int idx = blockIdx.x * blockDim.x + threadIdx.x;
    if (idx >= Hh * 1024) return;
    int h  = idx >> 10;
    int a  = (idx >> 5) & 31;
    int bb = idx & 31;
    double dx = log(fmax((double)a / 33.0, 1e-3));
    double dy = log(fmax((double)bb / 33.0, 1e-3));
    const float* w = wg_w + h * 64;
    double val = (double)wg_b[h];
    #pragma unroll
    for (int d = 0; d < 8; d++) {
        double dm = pow(1000.0, -(double)d / 8.0);
        double ax = 100.0 * dx * dm;
        double ay = 100.0 * dy * dm;
        val += sin(ax) * (double)w[d]      + sin(ay) * (double)w[8 + d]
             + cos(ax) * (double)w[32 + d] + cos(ay) * (double)w[40 + d];
    }
    #pragma unroll
    for (int d = 48; d < 64; d++) val += (double)w[d];
    val = fmax(val, 0.0);
    val = log(fmax(val, 1e-6));
    g_tab[idx] = (float)(val * 1.4426950408889634);   // * log2(e)
}

// ==========================================================================
// Tensor GEMM via mma.sync (bf16 hi/lo split, 3 MMAs per k16): C = A @ B^T
// mode 0: write Q/K/V as bf16 hi/lo into (b,h,n,d) buffers
// mode 1: A = g_att, out = C + bias (fp32)
// ==========================================================================
#define GP  80                 // smem row pitch in BYTES (40 bf16)
#define GTB (128 * GP)         // one tile: 10240 B
#define G_SMEM (8 * GTB)       // 2 buffers x {Ahi,Alo,Bhi,Blo}

__global__ __launch_bounds__(256, 1) void gemm_tc(const float* __restrict__ Ain,
                                                  const float* __restrict__ Bw,
                                                  int mode,
                                                  float* __restrict__ out,
                                                  const float* __restrict__ bias) {
    extern __shared__ char sm[];
    const float* A = (mode == 1) ? (const float*)g_att : Ain;
    int tid = threadIdx.x, lane = tid & 31, wid = tid >> 5;
    int wm = wid & 3, wn = wid >> 2;
    int n0 = blockIdx.x * 128, m0 = blockIdx.y * 128;
    uint32_t sb = smem_u32(sm);

    float C[2][8][4] = {};

    auto load_blk = [&](int kb, int bf) {
        int k0 = kb * 32;
        char* base = sm + bf * 4 * GTB;
        #pragma unroll
        for (int i = 0; i < 4; i++) {
            int idx = tid + i * 256;          // 0..1023
            int r = idx >> 3, c = (idx & 7) * 4;
            float4 v = make_float4(0.f, 0.f, 0.f, 0.f);
            int m = m0 + r;
            if (m < Mrows) v = *(const float4*)(A + (size_t)m * 512 + k0 + c);
            float e0, e1, e2, e3;
            uint32_t h01 = pack_hi2(v.x, v.y, e0, e1);
            uint32_t h23 = pack_hi2(v.z, v.w, e2, e3);
            *(uint2*)(base + r * GP + c * 2)       = make_uint2(h01, h23);
            *(uint2*)(base + GTB + r * GP + c * 2) = make_uint2(pack2(e0, e1), pack2(e2, e3));
            float4 w = *(const float4*)(Bw + (size_t)(n0 + r) * 512 + k0 + c);
            h01 = pack_hi2(w.x, w.y, e0, e1);
            h23 = pack_hi2(w.z, w.w, e2, e3);
            *(uint2*)(base + 2 * GTB + r * GP + c * 2) = make_uint2(h01, h23);
            *(uint2*)(base + 3 * GTB + r * GP + c * 2) = make_uint2(pack2(e0, e1), pack2(e2, e3));
        }
    };

    load_blk(0, 0);
    __syncthreads();

    #pragma unroll 1
    for (int kb = 0; kb < 16; kb++) {
        if (kb + 1 < 16) load_blk(kb + 1, (kb + 1) & 1);
        uint32_t tb = sb + (kb & 1) * 4 * GTB;
        #pragma unroll
        for (int ks = 0; ks < 2; ks++) {
            uint32_t ah[2][4], al[2][4];
            #pragma unroll
            for (int am = 0; am < 2; am++) {
                int row = wm * 32 + am * 16 + (lane & 15);
                int col = ks * 16 + ((lane >> 4) << 3);
                ldsm4(ah[am], tb + row * GP + col * 2);
                ldsm4(al[am], tb + GTB + row * GP + col * 2);
            }
            #pragma unroll
            for (int bp = 0; bp < 4; bp++) {
                int rown = wn * 64 + bp * 16 + (lane & 7) + ((lane >> 4) << 3);
                int col  = ks * 16 + (((lane >> 3) & 1) << 3);
                uint32_t th[4], tl[4];
                ldsm4(th, tb + 2 * GTB + rown * GP + col * 2);
                ldsm4(tl, tb + 3 * GTB + rown * GP + col * 2);
                #pragma unroll
                for (int s = 0; s < 2; s++) {
                    int bn = bp * 2 + s;
                    #pragma unroll
                    for (int am = 0; am < 2; am++) {
                        mma_bf16(C[am][bn], ah[am], th + s * 2);
                        mma_bf16(C[am][bn], ah[am], tl + s * 2);
                        mma_bf16(C[am][bn], al[am], th + s * 2);
                    }
                }
            }
        }
        __syncthreads();
    }

    // Epilogue
    int nbase = n0 + wn * 64;
    if (mode == 0) {
        int slot = nbase >> 9, h = (nbase >> 6) & 7;
        __nv_bfloat16 *dh, *dl;
        if (slot == 0)      { dh = g_qh; dl = g_ql; }
        else if (slot == 1) { dh = g_kh; dl = g_kl; }
        else                { dh = g_vh; dl = g_vl; }
        #pragma unroll
        for (int am = 0; am < 2; am++)
        #pragma unroll
        for (int rr = 0; rr < 2; rr++) {
            int m = m0 + wm * 32 + am * 16 + (lane >> 2) + rr * 8;
            if (m < Mrows) {
                int bidx = m / Nn, ii = m - bidx * Nn;
                size_t ro = (((size_t)(bidx * 8 + h)) * Nn + ii) * 64;
                #pragma unroll
                for (int bn = 0; bn < 8; bn++) {
                    int d = bn * 8 + (lane & 3) * 2;
                    float a = C[am][bn][rr * 2], b = C[am][bn][rr * 2 + 1];
                    float ea, eb;
                    uint32_t hi = pack_hi2(a, b, ea, eb);
                    uint32_t lo = pack2(ea, eb);
                    *(uint32_t*)(dh + ro + d) = hi;
                    *(uint32_t*)(dl + ro + d) = lo;
                }
            }
        }
    } else {
        #pragma unroll
        for (int am = 0; am < 2; am++)
        #pragma unroll
        for (int rr = 0; rr < 2; rr++) {
            int m = m0 + wm * 32 + am * 16 + (lane >> 2) + rr * 8;
            if (m < Mrows) {
                float* rp = out + (size_t)m * 512 + nbase;
                #pragma unroll
                for (int bn = 0; bn < 8; bn++) {
                    int d = bn * 8 + (lane & 3) * 2;
                    *(float2*)(rp + d) = make_float2(C[am][bn][rr * 2] + bias[nbase + d],
                                                     C[am][bn][rr * 2 + 1] + bias[nbase + d + 1]);
                }
            }
        }
    }
}

// ==========================================================================
// Flash attention on mma.sync, bf16 hi/lo inputs, cp.async double-buffered.
// Block = 256 thr (8 warps x 16 q-rows = 128 q rows), key tiles of 64.
// ==========================================================================
#define AP    144                       // smem row pitch bytes
#define A_BUF(bf, arr) (4096 + ((bf) * 4 + (arr)) * 9216)
#define A_SMEM (4096 + 8 * 9216)        // 77824 B
#define NTILE 17                        // ceil(1025/64)

__global__ __launch_bounds__(256) void attn_tc() {
    extern __shared__ char sm[];
    uint32_t sb = smem_u32(sm);
    int tid = threadIdx.x, lane = tid & 31, wid = tid >> 5;
    int bh = blockIdx.y, h = bh & 7, b = bh >> 3;
    int rowbase0 = blockIdx.x * 128;
    float* tab = (float*)sm;

    for (int i = tid; i < 1024; i += 256) tab[i] = g_tab[h * 1024 + i];

    // ---- stage Q (bf16 hi/lo) via cp.async, two 64-row passes
    uint32_t qh[4][4], ql[4][4];
    #pragma unroll 1
    for (int p = 0; p < 2; p++) {
        __syncthreads();
        #pragma unroll
        for (int i = 0; i < 4; i++) {
            int idx = tid + i * 256;            // 0..1023
            int arr = idx >> 9;                 // 0=hi 1=lo
            int rem = idx & 511;
            int r = rem >> 3, ck = rem & 7;
            int grow = rowbase0 + p * 64 + r;
            const __nv_bfloat16* base = arr ? g_ql : g_qh;
            const void* src = base + ((size_t)bh * Nn + (grow < Nn ? grow : 0)) * 64 + ck * 8;
            cp16(sb + A_BUF(0, arr) + r * AP + ck * 16, src, grow < Nn);
        }
        CP_COMMIT();
        CP_WAIT(0);
        __syncthreads();
        if ((wid >> 2) == p) {
            int rloc = (wid & 3) * 16 + (lane & 15);
            #pragma unroll
            for (int ks = 0; ks < 4; ks++) {
                int col = ks * 16 + ((lane >> 4) << 3);
                ldsm4(qh[ks], sb + A_BUF(0, 0) + rloc * AP + col * 2);
                ldsm4(ql[ks], sb + A_BUF(0, 1) + rloc * AP + col * 2);
            }
        }
    }
    __syncthreads();

    float O[8][4] = {};
    float mr0 = -1e30f, mr1 = -1e30f, lr0 = 0.f, lr1 = 0.f;
    int r0g = rowbase0 + wid * 16 + (lane >> 2);
    int r1g = r0g + 8;
    int ri0 = min(r0g, Nn - 1), ri1 = min(r1g, Nn - 1);
    int pxi0 = (ri0 - 1) >> 5, pyi0 = (ri0 - 1) & 31;
    int pxi1 = (ri1 - 1) >> 5, pyi1 = (ri1 - 1) & 31;
    const float c1 = 0.18033688011112042f;   // 0.125 * log2(e)

    // ---- K/V tile stager: 4 arrays (KH,KL,VH,VL) x 64 rows x 8 chunks
    auto stage = [&](int jt, int bf) {
        #pragma unroll
        for (int i = 0; i < 8; i++) {
            int idx = tid + i * 256;            // 0..2047
            int arr = idx >> 9;                 // 0..3
            int rem = idx & 511;
            int r = rem >> 3, ck = rem & 7;
            int j = jt + r;
            const __nv_bfloat16* base = (arr == 0) ? g_kh : (arr == 1) ? g_kl
                                      : (arr == 2) ? g_vh : g_vl;
            const void* src = base + ((size_t)bh * Nn + (j < Nn ? j : 0)) * 64 + ck * 8;
            cp16(sb + A_BUF(bf, arr) + r * AP + ck * 16, src, j < Nn);
        }
        CP_COMMIT();
    };

    stage(0, 0);

    #pragma unroll 1
    for (int t = 0; t < NTILE; t++) {
        int bf = t & 1;
        if (t + 1 < NTILE) { stage(t * 64 + 64, bf ^ 1); CP_WAIT(1); }
        else               { CP_WAIT(0); }
        __syncthreads();
        int jt = t * 64;
        uint32_t kh_b = sb + A_BUF(bf, 0), kl_b = sb + A_BUF(bf, 1);
        uint32_t vh_b = sb + A_BUF(bf, 2), vl_b = sb + A_BUF(bf, 3);

        // ---- scores S = Q @ K^T (3-term split)
        float S[8][4] = {};
        #pragma unroll
        for (int ks = 0; ks < 4; ks++) {
            #pragma unroll
            for (int bp = 0; bp < 4; bp++) {
                int rown = bp * 16 + (lane & 7) + ((lane >> 4) << 3);
                int col  = ks * 16 + (((lane >> 3) & 1) << 3);
                uint32_t th[4], tl[4];
                ldsm4(th, kh_b + rown * AP + col * 2);
                ldsm4(tl, kl_b + rown * AP + col * 2);
                #pragma unroll
                for (int s = 0; s < 2; s++) {
                    mma_bf16(S[bp * 2 + s], qh[ks], th + s * 2);
                    mma_bf16(S[bp * 2 + s], qh[ks], tl + s * 2);
                    mma_bf16(S[bp * 2 + s], ql[ks], th + s * 2);
                }
            }
        }

        // ---- bias + mask + online softmax (exp2 domain)
        float mx0 = -1e30f, mx1 = -1e30f;
        #pragma unroll
        for (int bn = 0; bn < 8; bn++) {
            #pragma unroll
            for (int v = 0; v < 4; v++) {
                int j = jt + bn * 8 + (lane & 3) * 2 + (v & 1);
                float y;
                if (j >= Nn) {
                    y = -1e30f;
                } else {
                    int ri  = (v < 2) ? ri0 : ri1;
                    float bias = 0.f;
                    if (j > 0 && ri > 0) {
                        int pxj = (j - 1) >> 5, pyj = (j - 1) & 31;
                        int ax = ((v < 2) ? pxi0 : pxi1) - pxj; ax = ax < 0 ? -ax : ax;
                        int ay = ((v < 2) ? pyi0 : pyi1) - pyj; ay = ay < 0 ? -ay : ay;
                        bias = tab[ax * 32 + ay];
                    }
                    y = S[bn][v] * c1 + bias;
                }
                S[bn][v] = y;
                if (v < 2) mx0 = fmaxf(mx0, y); else mx1 = fmaxf(mx1, y);
            }
        }
        mx0 = fmaxf(mx0, __shfl_xor_sync(0xffffffffu, mx0, 1));
        mx0 = fmaxf(mx0, __shfl_xor_sync(0xffffffffu, mx0, 2));
        mx1 = fmaxf(mx1, __shfl_xor_sync(0xffffffffu, mx1, 1));
        mx1 = fmaxf(mx1, __shfl_xor_sync(0xffffffffu, mx1, 2));
        float nm0 = fmaxf(mr0, mx0), nm1 = fmaxf(mr1, mx1);
        float sc0 = ex2f(mr0 - nm0), sc1 = ex2f(mr1 - nm1);
        mr0 = nm0; mr1 = nm1;
        lr0 *= sc0; lr1 *= sc1;
        #pragma unroll
        for (int bn = 0; bn < 8; bn++) {
            O[bn][0] *= sc0; O[bn][1] *= sc0;
            O[bn][2] *= sc1; O[bn][3] *= sc1;
        }
        #pragma unroll
        for (int bn = 0; bn < 8; bn++) {
            float p0 = ex2f(S[bn][0] - mr0); lr0 += p0; S[bn][0] = p0;
            float p1 = ex2f(S[bn][1] - mr0); lr0 += p1; S[bn][1] = p1;
            float p2 = ex2f(S[bn][2] - mr1); lr1 += p2; S[bn][2] = p2;
            float p3 = ex2f(S[bn][3] - mr1); lr1 += p3; S[bn][3] = p3;
        }

        // ---- O += P @ V (P in regs as A-frags, V via trans-ldmatrix, split)
        #pragma unroll
        for (int tt = 0; tt < 4; tt++) {
            uint32_t aph[4], apl[4];
            float e0, e1, e2, e3;
            aph[0] = pack_hi2(S[2 * tt][0], S[2 * tt][1], e0, e1);
            aph[1] = pack_hi2(S[2 * tt][2], S[2 * tt][3], e2, e3);
            apl[0] = pack2(e0, e1); apl[1] = pack2(e2, e3);
            aph[2] = pack_hi2(S[2 * tt + 1][0], S[2 * tt + 1][1], e0, e1);
            aph[3] = pack_hi2(S[2 * tt + 1][2], S[2 * tt + 1][3], e2, e3);
            apl[2] = pack2(e0, e1); apl[3] = pack2(e2, e3);
            #pragma unroll
            for (int dp = 0; dp < 4; dp++) {
                int rowv = tt * 16 + (lane & 7) + (((lane >> 3) & 1) << 3);
                int colv = dp * 16 + ((lane >> 4) << 3);
                uint32_t vh4[4], vl4[4];
                ldsm4t(vh4, vh_b + rowv * AP + colv * 2);
                ldsm4t(vl4, vl_b + rowv * AP + colv * 2);
                #pragma unroll
                for (int s = 0; s < 2; s++) {
                    mma_bf16(O[dp * 2 + s], aph, vh4 + s * 2);
                    mma_bf16(O[dp * 2 + s], aph, vl4 + s * 2);
                    mma_bf16(O[dp * 2 + s], apl, vh4 + s * 2);
                }
            }
        }
        __syncthreads();
    }

    // ---- finalize
    lr0 += __shfl_xor_sync(0xffffffffu, lr0, 1);
    lr0 += __shfl_xor_sync(0xffffffffu, lr0, 2);
    lr1 += __shfl_xor_sync(0xffffffffu, lr1, 1);
    lr1 += __shfl_xor_sync(0xffffffffu, lr1, 2);
    float inv0 = 1.f / lr0, inv1 = 1.f / lr1;
    if (r0g < Nn) {
        float* rp = g_att + ((size_t)(b * Nn + r0g)) * 512 + h * 64;
        #pragma unroll
        for (int bn = 0; bn < 8; bn++) {
            int d = bn * 8 + (lane & 3) * 2;
            *(float2*)(rp + d) = make_float2(O[bn][0] * inv0, O[bn][1] * inv0);
        }
    }
    if (r1g < Nn) {
        float* rp = g_att + ((size_t)(b * Nn + r1g)) * 512 + h * 64;
        #pragma unroll
        for (int bn = 0; bn < 8; bn++) {
            int d = bn * 8 + (lane & 3) * 2;
            *(float2*)(rp + d) = make_float2(O[bn][2] * inv1, O[bn][3] * inv1);
        }
    }
}

// ==========================================================================
extern "C" void kernel_launch(void* const* d_in, const int* in_sizes, int n_in,
                              void* d_out, int out_size) {
    const float* x      = (const float*)d_in[0];
    const float* qkv_w  = (const float*)d_in[1];
    const float* proj_w = (const float*)d_in[2];
    const float* proj_b = (const float*)d_in[3];
    const float* wg_w   = (const float*)d_in[4];
    const float* wg_b   = (const float*)d_in[5];
    float* out = (float*)d_out;

    cudaFuncSetAttribute(gemm_tc, cudaFuncAttributeMaxDynamicSharedMemorySize, G_SMEM);
    cudaFuncSetAttribute(attn_tc, cudaFuncAttributeMaxDynamicSharedMemorySize, A_SMEM);

    tab_kernel<<<32, 256>>>(wg_w, wg_b);
    gemm_tc<<<dim3(1536 / 128, (Mrows + 127) / 128), 256, G_SMEM>>>(x, qkv_w, 0, nullptr, nullptr);
    attn_tc<<<dim3((Nn + 127) / 128, Bn * Hh), 256, A_SMEM>>>();
    gemm_tc<<<dim3(512 / 128, (Mrows + 127) / 128), 256, G_SMEM>>>(nullptr, proj_w, 1, out, proj_b);
}

// round 10
// speedup vs baseline: 1.3557x; 1.3557x over previous
#include <cuda_runtime.h>
#include <cuda_bf16.h>
#include <math.h>
#include <stdint.h>

// Problem constants
#define Bn 8
#define Nn 1025
#define Cc 512
#define Hh 8
#define HD 64
#define Mrows (Bn*Nn)   // 8200

// Scratch: device globals (no cudaMalloc allowed)
__device__ __nv_bfloat16 g_qh[(size_t)Bn*Hh*Nn*HD];
__device__ __nv_bfloat16 g_ql[(size_t)Bn*Hh*Nn*HD];
__device__ __nv_bfloat16 g_kh[(size_t)Bn*Hh*Nn*HD];
__device__ __nv_bfloat16 g_kl[(size_t)Bn*Hh*Nn*HD];
__device__ __nv_bfloat16 g_vh[(size_t)Bn*Hh*Nn*HD];
__device__ __nv_bfloat16 g_vl[(size_t)Bn*Hh*Nn*HD];
__device__ float g_att[(size_t)Bn*Nn*Cc];      // (b,n,c) pre-projection
__device__ float g_tab[Hh*32*32];              // bias table, pre-scaled by log2(e)

// ==========================================================================
// Helpers (base-target PTX only: mma.sync / ldmatrix / cp.async)
// ==========================================================================
__device__ __forceinline__ uint32_t smem_u32(const void* p) {
    uint32_t a;
    asm("{ .reg .u64 t; cvta.to.shared.u64 t, %1; cvt.u32.u64 %0, t; }" : "=r"(a) : "l"(p));
    return a;
}
__device__ __forceinline__ void ldsm4(uint32_t* r, uint32_t a) {
    asm volatile("ldmatrix.sync.aligned.m8n8.x4.shared.b16 {%0,%1,%2,%3}, [%4];"
        : "=r"(r[0]), "=r"(r[1]), "=r"(r[2]), "=r"(r[3]) : "r"(a));
}
__device__ __forceinline__ void ldsm4t(uint32_t* r, uint32_t a) {
    asm volatile("ldmatrix.sync.aligned.m8n8.x4.trans.shared.b16 {%0,%1,%2,%3}, [%4];"
        : "=r"(r[0]), "=r"(r[1]), "=r"(r[2]), "=r"(r[3]) : "r"(a));
}
__device__ __forceinline__ void mma_bf16(float* c, const uint32_t* a, const uint32_t* b) {
    asm volatile("mma.sync.aligned.m16n8k16.row.col.f32.bf16.bf16.f32 "
        "{%0,%1,%2,%3}, {%4,%5,%6,%7}, {%8,%9}, {%0,%1,%2,%3};"
        : "+f"(c[0]), "+f"(c[1]), "+f"(c[2]), "+f"(c[3])
        : "r"(a[0]), "r"(a[1]), "r"(a[2]), "r"(a[3]), "r"(b[0]), "r"(b[1]));
}
__device__ __forceinline__ float ex2f(float x) {
    float y; asm("ex2.approx.f32 %0, %1;" : "=f"(y) : "f"(x)); return y;
}
__device__ __forceinline__ uint32_t pack_hi2(float a, float b, float& ra, float& rb) {
    __nv_bfloat16 ha = __float2bfloat16_rn(a);
    __nv_bfloat16 hb = __float2bfloat16_rn(b);
    ra = a - __bfloat162float(ha);
    rb = b - __bfloat162float(hb);
    __nv_bfloat162 p(ha, hb);
    return *reinterpret_cast<uint32_t*>(&p);
}
__device__ __forceinline__ uint32_t pack2(float a, float b) {
    __nv_bfloat162 p(__float2bfloat16_rn(a), __float2bfloat16_rn(b));
    return *reinterpret_cast<uint32_t*>(&p);
}
__device__ __forceinline__ void cp16(uint32_t dst, const void* src, bool valid) {
    int sz = valid ? 16 : 0;
    asm volatile("cp.async.cg.shared.global [%0], [%1], 16, %2;"
        :: "r"(dst), "l"(src), "r"(sz) : "memory");
}
#define CP_COMMIT() asm volatile("cp.async.commit_group;" ::: "memory")
#define CP_WAIT(N)  asm volatile("cp.async.wait_group %0;" :: "n"(N) : "memory")

// ==========================================================================
// Bias table (collapsed geometry): stored pre-multiplied by log2(e)
// ==========================================================================
__global__ void tab_kernel(const float* __restrict__ wg_w,
                           const float* __restrict__ wg_b) {
    int idx = blockIdx.x * blockDim.x + threadIdx.x;
    if (idx >= Hh * 1024) return;
    int h  = idx >> 10;
    int a  = (idx >> 5) & 31;
    int bb = idx & 31;
    double dx = log(fmax((double)a / 33.0, 1e-3));
    double dy = log(fmax((double)bb / 33.0, 1e-3));
    const float* w = wg_w + h * 64;
    double val = (double)wg_b[h];
    #pragma unroll
    for (int d = 0; d < 8; d++) {
        double dm = pow(1000.0, -(double)d / 8.0);
        double ax = 100.0 * dx * dm;
        double ay = 100.0 * dy * dm;
        val += sin(ax) * (double)w[d]      + sin(ay) * (double)w[8 + d]
             + cos(ax) * (double)w[32 + d] + cos(ay) * (double)w[40 + d];
    }
    #pragma unroll
    for (int d = 48; d < 64; d++) val += (double)w[d];
    val = fmax(val, 0.0);
    val = log(fmax(val, 1e-6));
    g_tab[idx] = (float)(val * 1.4426950408889634);   // * log2(e)
}

// ==========================================================================
// Tensor GEMM via mma.sync (bf16 hi/lo split, 3 MMAs per k16): C = A @ B^T
// mode 0: write Q/K/V as bf16 hi/lo into (b,h,n,d) buffers
// mode 1: A = g_att, out = C + bias (fp32)
// ==========================================================================
#define GP  80                 // smem row pitch in BYTES (40 bf16)
#define GTB (128 * GP)         // one tile: 10240 B
#define G_SMEM (8 * GTB)       // 2 buffers x {Ahi,Alo,Bhi,Blo}

__global__ __launch_bounds__(256, 2) void gemm_tc(const float* __restrict__ Ain,
                                                  const float* __restrict__ Bw,
                                                  int mode,
                                                  float* __restrict__ out,
                                                  const float* __restrict__ bias) {
    extern __shared__ char sm[];
    const float* A = (mode == 1) ? (const float*)g_att : Ain;
    int tid = threadIdx.x, lane = tid & 31, wid = tid >> 5;
    int wm = wid & 3, wn = wid >> 2;
    int n0 = blockIdx.x * 128, m0 = blockIdx.y * 128;
    uint32_t sb = smem_u32(sm);

    float C[2][8][4] = {};

    auto load_blk = [&](int kb, int bf) {
        int k0 = kb * 32;
        char* base = sm + bf * 4 * GTB;
        #pragma unroll
        for (int i = 0; i < 4; i++) {
            int idx = tid + i * 256;          // 0..1023
            int r = idx >> 3, c = (idx & 7) * 4;
            float4 v = make_float4(0.f, 0.f, 0.f, 0.f);
            int m = m0 + r;
            if (m < Mrows) v = *(const float4*)(A + (size_t)m * 512 + k0 + c);
            float e0, e1, e2, e3;
            uint32_t h01 = pack_hi2(v.x, v.y, e0, e1);
            uint32_t h23 = pack_hi2(v.z, v.w, e2, e3);
            *(uint2*)(base + r * GP + c * 2)       = make_uint2(h01, h23);
            *(uint2*)(base + GTB + r * GP + c * 2) = make_uint2(pack2(e0, e1), pack2(e2, e3));
            float4 w = *(const float4*)(Bw + (size_t)(n0 + r) * 512 + k0 + c);
            h01 = pack_hi2(w.x, w.y, e0, e1);
            h23 = pack_hi2(w.z, w.w, e2, e3);
            *(uint2*)(base + 2 * GTB + r * GP + c * 2) = make_uint2(h01, h23);
            *(uint2*)(base + 3 * GTB + r * GP + c * 2) = make_uint2(pack2(e0, e1), pack2(e2, e3));
        }
    };

    load_blk(0, 0);
    __syncthreads();

    #pragma unroll 1
    for (int kb = 0; kb < 16; kb++) {
        if (kb + 1 < 16) load_blk(kb + 1, (kb + 1) & 1);
        uint32_t tb = sb + (kb & 1) * 4 * GTB;
        #pragma unroll
        for (int ks = 0; ks < 2; ks++) {
            uint32_t ah[2][4], al[2][4];
            #pragma unroll
            for (int am = 0; am < 2; am++) {
                int row = wm * 32 + am * 16 + (lane & 15);
                int col = ks * 16 + ((lane >> 4) << 3);
                ldsm4(ah[am], tb + row * GP + col * 2);
                ldsm4(al[am], tb + GTB + row * GP + col * 2);
            }
            #pragma unroll
            for (int bp = 0; bp < 4; bp++) {
                int rown = wn * 64 + bp * 16 + (lane & 7) + ((lane >> 4) << 3);
                int col  = ks * 16 + (((lane >> 3) & 1) << 3);
                uint32_t th[4], tl[4];
                ldsm4(th, tb + 2 * GTB + rown * GP + col * 2);
                ldsm4(tl, tb + 3 * GTB + rown * GP + col * 2);
                #pragma unroll
                for (int s = 0; s < 2; s++) {
                    int bn = bp * 2 + s;
                    #pragma unroll
                    for (int am = 0; am < 2; am++) {
                        mma_bf16(C[am][bn], ah[am], th + s * 2);
                        mma_bf16(C[am][bn], ah[am], tl + s * 2);
                        mma_bf16(C[am][bn], al[am], th + s * 2);
                    }
                }
            }
        }
        __syncthreads();
    }

    // Epilogue
    int nbase = n0 + wn * 64;
    if (mode == 0) {
        int slot = nbase >> 9, h = (nbase >> 6) & 7;
        __nv_bfloat16 *dh, *dl;
        if (slot == 0)      { dh = g_qh; dl = g_ql; }
        else if (slot == 1) { dh = g_kh; dl = g_kl; }
        else                { dh = g_vh; dl = g_vl; }
        #pragma unroll
        for (int am = 0; am < 2; am++)
        #pragma unroll
        for (int rr = 0; rr < 2; rr++) {
            int m = m0 + wm * 32 + am * 16 + (lane >> 2) + rr * 8;
            if (m < Mrows) {
                int bidx = m / Nn, ii = m - bidx * Nn;
                size_t ro = (((size_t)(bidx * 8 + h)) * Nn + ii) * 64;
                #pragma unroll
                for (int bn = 0; bn < 8; bn++) {
                    int d = bn * 8 + (lane & 3) * 2;
                    float a = C[am][bn][rr * 2], b = C[am][bn][rr * 2 + 1];
                    float ea, eb;
                    uint32_t hi = pack_hi2(a, b, ea, eb);
                    uint32_t lo = pack2(ea, eb);
                    *(uint32_t*)(dh + ro + d) = hi;
                    *(uint32_t*)(dl + ro + d) = lo;
                }
            }
        }
    } else {
        #pragma unroll
        for (int am = 0; am < 2; am++)
        #pragma unroll
        for (int rr = 0; rr < 2; rr++) {
            int m = m0 + wm * 32 + am * 16 + (lane >> 2) + rr * 8;
            if (m < Mrows) {
                float* rp = out + (size_t)m * 512 + nbase;
                #pragma unroll
                for (int bn = 0; bn < 8; bn++) {
                    int d = bn * 8 + (lane & 3) * 2;
                    *(float2*)(rp + d) = make_float2(C[am][bn][rr * 2] + bias[nbase + d],
                                                     C[am][bn][rr * 2 + 1] + bias[nbase + d + 1]);
                }
            }
        }
    }
}

// ==========================================================================
// Flash attention on mma.sync: 128 threads (4 warps), q-tile 64, k-tile 32,
// double-buffered cp.async, 3 CTAs/SM target.
// ==========================================================================
#define AP    144                       // smem row pitch bytes
#define KVB   (32 * AP)                 // 4608 per array
#define A_KV(bf, arr) (4096 + ((bf) * 4 + (arr)) * KVB)
#define A_SMEM (4096 + 8 * KVB)         // 40960 B
#define NKT 33                          // ceil(1025/32)

__global__ __launch_bounds__(128, 3) void attn_tc() {
    extern __shared__ char sm[];
    uint32_t sb = smem_u32(sm);
    int tid = threadIdx.x, lane = tid & 31, wid = tid >> 5;
    int bh = blockIdx.y, h = bh & 7, b = bh >> 3;
    int rowbase = blockIdx.x * 64;
    float* tab = (float*)sm;

    for (int i = tid; i < 1024; i += 128) tab[i] = g_tab[h * 1024 + i];

    // ---- stage Q (64 rows, hi/lo) via cp.async into KV buffer region
    {
        #pragma unroll
        for (int i = 0; i < 8; i++) {
            int idx = tid + i * 128;            // 0..1023
            int arr = idx >> 9;                 // 0=hi 1=lo
            int rem = idx & 511;
            int r = rem >> 3, ck = rem & 7;
            int grow = rowbase + r;
            const __nv_bfloat16* base = arr ? g_ql : g_qh;
            const void* src = base + ((size_t)bh * Nn + (grow < Nn ? grow : 0)) * 64 + ck * 8;
            cp16(sb + 4096 + arr * 9216 + r * AP + ck * 16, src, grow < Nn);
        }
        CP_COMMIT();
        CP_WAIT(0);
    }
    __syncthreads();

    uint32_t qh[4][4], ql[4][4];
    {
        int rloc = wid * 16 + (lane & 15);
        #pragma unroll
        for (int ks = 0; ks < 4; ks++) {
            int col = ks * 16 + ((lane >> 4) << 3);
            ldsm4(qh[ks], sb + 4096 + rloc * AP + col * 2);
            ldsm4(ql[ks], sb + 4096 + 9216 + rloc * AP + col * 2);
        }
    }
    __syncthreads();

    float O[8][4] = {};
    float mr0 = -1e30f, mr1 = -1e30f, lr0 = 0.f, lr1 = 0.f;
    int r0g = rowbase + wid * 16 + (lane >> 2);
    int r1g = r0g + 8;
    int ri0 = min(r0g, Nn - 1), ri1 = min(r1g, Nn - 1);
    int pxi0 = (ri0 - 1) >> 5, pyi0 = (ri0 - 1) & 31;
    int pxi1 = (ri1 - 1) >> 5, pyi1 = (ri1 - 1) & 31;
    const float c1 = 0.18033688011112042f;   // 0.125 * log2(e)

    // ---- K/V tile stager: 4 arrays (KH,KL,VH,VL) x 32 rows x 8 chunks
    auto stage = [&](int jt, int bf) {
        #pragma unroll
        for (int i = 0; i < 8; i++) {
            int idx = tid + i * 128;            // 0..1023
            int arr = idx >> 8;                 // 0..3
            int rem = idx & 255;
            int r = rem >> 3, ck = rem & 7;
            int j = jt + r;
            const __nv_bfloat16* base = (arr == 0) ? g_kh : (arr == 1) ? g_kl
                                      : (arr == 2) ? g_vh : g_vl;
            const void* src = base + ((size_t)bh * Nn + (j < Nn ? j : 0)) * 64 + ck * 8;
            cp16(sb + A_KV(bf, arr) + r * AP + ck * 16, src, j < Nn);
        }
        CP_COMMIT();
    };

    stage(0, 0);

    #pragma unroll 1
    for (int t = 0; t < NKT; t++) {
        int bf = t & 1;
        if (t + 1 < NKT) { stage(t * 32 + 32, bf ^ 1); CP_WAIT(1); }
        else             { CP_WAIT(0); }
        __syncthreads();
        int jt = t * 32;
        uint32_t kh_b = sb + A_KV(bf, 0), kl_b = sb + A_KV(bf, 1);
        uint32_t vh_b = sb + A_KV(bf, 2), vl_b = sb + A_KV(bf, 3);

        // ---- scores S = Q @ K^T (3-term split)
        float S[4][4] = {};
        #pragma unroll
        for (int ks = 0; ks < 4; ks++) {
            #pragma unroll
            for (int bp = 0; bp < 2; bp++) {
                int rown = bp * 16 + (lane & 7) + ((lane >> 4) << 3);
                int col  = ks * 16 + (((lane >> 3) & 1) << 3);
                uint32_t th[4], tl[4];
                ldsm4(th, kh_b + rown * AP + col * 2);
                ldsm4(tl, kl_b + rown * AP + col * 2);
                #pragma unroll
                for (int s = 0; s < 2; s++) {
                    mma_bf16(S[bp * 2 + s], qh[ks], th + s * 2);
                    mma_bf16(S[bp * 2 + s], qh[ks], tl + s * 2);
                    mma_bf16(S[bp * 2 + s], ql[ks], th + s * 2);
                }
            }
        }

        // ---- bias + mask + online softmax (exp2 domain)
        float mx0 = -1e30f, mx1 = -1e30f;
        #pragma unroll
        for (int bn = 0; bn < 4; bn++) {
            #pragma unroll
            for (int v = 0; v < 4; v++) {
                int j = jt + bn * 8 + (lane & 3) * 2 + (v & 1);
                float y;
                if (j >= Nn) {
                    y = -1e30f;
                } else {
                    int ri  = (v < 2) ? ri0 : ri1;
                    float bias = 0.f;
                    if (j > 0 && ri > 0) {
                        int pxj = (j - 1) >> 5, pyj = (j - 1) & 31;
                        int px = (v < 2) ? pxi0 : pxi1;
                        int py = (v < 2) ? pyi0 : pyi1;
                        bias = tab[__usad(px, pxj, 0) * 32 + __usad(py, pyj, 0)];
                    }
                    y = S[bn][v] * c1 + bias;
                }
                S[bn][v] = y;
                if (v < 2) mx0 = fmaxf(mx0, y); else mx1 = fmaxf(mx1, y);
            }
        }
        mx0 = fmaxf(mx0, __shfl_xor_sync(0xffffffffu, mx0, 1));
        mx0 = fmaxf(mx0, __shfl_xor_sync(0xffffffffu, mx0, 2));
        mx1 = fmaxf(mx1, __shfl_xor_sync(0xffffffffu, mx1, 1));
        mx1 = fmaxf(mx1, __shfl_xor_sync(0xffffffffu, mx1, 2));
        float nm0 = fmaxf(mr0, mx0), nm1 = fmaxf(mr1, mx1);
        float sc0 = ex2f(mr0 - nm0), sc1 = ex2f(mr1 - nm1);
        mr0 = nm0; mr1 = nm1;
        lr0 *= sc0; lr1 *= sc1;
        #pragma unroll
        for (int bn = 0; bn < 8; bn++) {
            O[bn][0] *= sc0; O[bn][1] *= sc0;
            O[bn][2] *= sc1; O[bn][3] *= sc1;
        }
        #pragma unroll
        for (int bn = 0; bn < 4; bn++) {
            float p0 = ex2f(S[bn][0] - mr0); lr0 += p0; S[bn][0] = p0;
            float p1 = ex2f(S[bn][1] - mr0); lr0 += p1; S[bn][1] = p1;
            float p2 = ex2f(S[bn][2] - mr1); lr1 += p2; S[bn][2] = p2;
            float p3 = ex2f(S[bn][3] - mr1); lr1 += p3; S[bn][3] = p3;
        }

        // ---- O += P @ V (P in regs as A-frags, V via trans-ldmatrix, split)
        #pragma unroll
        for (int tt = 0; tt < 2; tt++) {
            uint32_t aph[4], apl[4];
            float e0, e1, e2, e3;
            aph[0] = pack_hi2(S[2 * tt][0], S[2 * tt][1], e0, e1);
            aph[1] = pack_hi2(S[2 * tt][2], S[2 * tt][3], e2, e3);
            apl[0] = pack2(e0, e1); apl[1] = pack2(e2, e3);
            aph[2] = pack_hi2(S[2 * tt + 1][0], S[2 * tt + 1][1], e0, e1);
            aph[3] = pack_hi2(S[2 * tt + 1][2], S[2 * tt + 1][3], e2, e3);
            apl[2] = pack2(e0, e1); apl[3] = pack2(e2, e3);
            #pragma unroll
            for (int dp = 0; dp < 4; dp++) {
                int rowv = tt * 16 + (lane & 7) + (((lane >> 3) & 1) << 3);
                int colv = dp * 16 + ((lane >> 4) << 3);
                uint32_t vh4[4], vl4[4];
                ldsm4t(vh4, vh_b + rowv * AP + colv * 2);
                ldsm4t(vl4, vl_b + rowv * AP + colv * 2);
                #pragma unroll
                for (int s = 0; s < 2; s++) {
                    mma_bf16(O[dp * 2 + s], aph, vh4 + s * 2);
                    mma_bf16(O[dp * 2 + s], aph, vl4 + s * 2);
                    mma_bf16(O[dp * 2 + s], apl, vh4 + s * 2);
                }
            }
        }
        __syncthreads();
    }

    // ---- finalize
    lr0 += __shfl_xor_sync(0xffffffffu, lr0, 1);
    lr0 += __shfl_xor_sync(0xffffffffu, lr0, 2);
    lr1 += __shfl_xor_sync(0xffffffffu, lr1, 1);
    lr1 += __shfl_xor_sync(0xffffffffu, lr1, 2);
    float inv0 = 1.f / lr0, inv1 = 1.f / lr1;
    if (r0g < Nn) {
        float* rp = g_att + ((size_t)(b * Nn + r0g)) * 512 + h * 64;
        #pragma unroll
        for (int bn = 0; bn < 8; bn++) {
            int d = bn * 8 + (lane & 3) * 2;
            *(float2*)(rp + d) = make_float2(O[bn][0] * inv0, O[bn][1] * inv0);
        }
    }
    if (r1g < Nn) {
        float* rp = g_att + ((size_t)(b * Nn + r1g)) * 512 + h * 64;
        #pragma unroll
        for (int bn = 0; bn < 8; bn++) {
            int d = bn * 8 + (lane & 3) * 2;
            *(float2*)(rp + d) = make_float2(O[bn][2] * inv1, O[bn][3] * inv1);
        }
    }
}

// ==========================================================================
extern "C" void kernel_launch(void* const* d_in, const int* in_sizes, int n_in,
                              void* d_out, int out_size) {
    const float* x      = (const float*)d_in[0];
    const float* qkv_w  = (const float*)d_in[1];
    const float* proj_w = (const float*)d_in[2];
    const float* proj_b = (const float*)d_in[3];
    const float* wg_w   = (const float*)d_in[4];
    const float* wg_b   = (const float*)d_in[5];
    float* out = (float*)d_out;

    cudaFuncSetAttribute(gemm_tc, cudaFuncAttributeMaxDynamicSharedMemorySize, G_SMEM);
    cudaFuncSetAttribute(attn_tc, cudaFuncAttributeMaxDynamicSharedMemorySize, A_SMEM);

    tab_kernel<<<32, 256>>>(wg_w, wg_b);
    gemm_tc<<<dim3(1536 / 128, (Mrows + 127) / 128), 256, G_SMEM>>>(x, qkv_w, 0, nullptr, nullptr);
    attn_tc<<<dim3((Nn + 63) / 64, Bn * Hh), 128, A_SMEM>>>();
    gemm_tc<<<dim3(512 / 128, (Mrows + 127) / 128), 256, G_SMEM>>>(nullptr, proj_w, 1, out, proj_b);
}